// round 2
// baseline (speedup 1.0000x reference)
#include <cuda_runtime.h>

#define N_ROWS 1024
#define T_LEN  2048
#define E_NUM  16384
#define K_TAPS 32
#define TPB    128            // threads per block
#define TOUT   16             // outputs (t values) per thread
#define MAX_B  96             // max experts per dst bucket (binomial(16384,1/1024): mean 16, sigma 4)

// ---------------------------------------------------------------------------
// One block per dst row n:
//   Phase A: scan dst[] (64KB, L1/L2-resident), build sorted expert list in smem.
//   Phase B: for each expert e in the list: stage x[src[e]] row in smem
//            (register double-buffered prefetch), depthwise causal conv,
//            accumulate in registers.
//   Phase C: out[n,:] = x[n,:] + acc.  No atomics anywhere.
// ---------------------------------------------------------------------------
__global__ __launch_bounds__(TPB, 4)
void conv_route_kernel(const float* __restrict__ x,
                       const float* __restrict__ w,
                       const int*   __restrict__ src,
                       const int*   __restrict__ dst,
                       float*       __restrict__ out) {
    __shared__ __align__(16) float xs[K_TAPS + T_LEN];  // xs[32+t] = row[t]; xs[0..31]=0
    __shared__ float wsh[K_TAPS];
    __shared__ int   lst[MAX_B];
    __shared__ int   scn[TPB];

    const int tid = threadIdx.x;
    const int n   = blockIdx.x;

    if (tid < K_TAPS) xs[tid] = 0.0f;     // causal halo, never overwritten

    // ---------------- Phase A: routing discovery --------------------------
    // Thread tid owns e in [tid*128, tid*128+128), read as 32 int4.
    const int4* d4 = (const int4*)dst;
    int cnt = 0;
#pragma unroll 8
    for (int c = 0; c < 32; ++c) {
        int4 v = d4[tid * 32 + c];
        cnt += (v.x == n) + (v.y == n) + (v.z == n) + (v.w == n);
    }
    scn[tid] = cnt;
    __syncthreads();
    // Hillis-Steele inclusive scan over 128 threads
    for (int ofs = 1; ofs < TPB; ofs <<= 1) {
        int a = (tid >= ofs) ? scn[tid - ofs] : 0;
        __syncthreads();
        scn[tid] += a;
        __syncthreads();
    }
    int excl  = scn[tid] - cnt;
    int total = scn[TPB - 1];
    if (total > MAX_B) total = MAX_B;     // statistically impossible; OOB guard
    // Pass 2: re-read (L1 hits) and compact in ascending-e order.
    {
        int pos = excl;
#pragma unroll 8
        for (int c = 0; c < 32; ++c) {
            int4 v = d4[tid * 32 + c];
            int  e0 = tid * 128 + c * 4;
            if (v.x == n && pos < MAX_B) lst[pos++] = e0;
            if (v.y == n && pos < MAX_B) lst[pos++] = e0 + 1;
            if (v.z == n && pos < MAX_B) lst[pos++] = e0 + 2;
            if (v.w == n && pos < MAX_B) lst[pos++] = e0 + 3;
        }
    }
    __syncthreads();

    // ---------------- Phase B: conv + accumulate --------------------------
    float acc[TOUT];
#pragma unroll
    for (int j = 0; j < TOUT; ++j) acc[j] = 0.0f;

    // Register double-buffer: prefetch first expert's row (4 float4/thread) + weights.
    float4 s0, s1, s2, s3;
    float  wreg = 0.0f;
    if (0 < total) {
        int e = lst[0];
        const float4* row = (const float4*)(x + (size_t)src[e] * T_LEN);
        s0 = row[tid];
        s1 = row[tid + 128];
        s2 = row[tid + 256];
        s3 = row[tid + 384];
        if (tid < K_TAPS) wreg = w[e * K_TAPS + tid];
    }

    for (int i = 0; i < total; ++i) {
        __syncthreads();                              // prior window reads done
        float4* xs4w = (float4*)(xs + K_TAPS);
        xs4w[tid]       = s0;
        xs4w[tid + 128] = s1;
        xs4w[tid + 256] = s2;
        xs4w[tid + 384] = s3;
        if (tid < K_TAPS) wsh[tid] = wreg;
        __syncthreads();

        if (i + 1 < total) {                          // prefetch next expert
            int e = lst[i + 1];
            const float4* row = (const float4*)(x + (size_t)src[e] * T_LEN);
            s0 = row[tid];
            s1 = row[tid + 128];
            s2 = row[tid + 256];
            s3 = row[tid + 384];
            if (tid < K_TAPS) wreg = w[e * K_TAPS + tid];
        }

        // Window: thread owns t0 = 16*tid .. t0+15; needs xs[t0 .. t0+47]
        // (xv[m] = xs[t0+m]; output j uses xv[32+j-k], k=0..31 -> m in [1,47]).
        float xv[48];
        const float4* xs4 = (const float4*)xs;
#pragma unroll
        for (int c = 0; c < 12; ++c) {
            float4 v = xs4[4 * tid + c];
            xv[4 * c + 0] = v.x; xv[4 * c + 1] = v.y;
            xv[4 * c + 2] = v.z; xv[4 * c + 3] = v.w;
        }

#pragma unroll
        for (int k = 0; k < K_TAPS; ++k) {
            float wk = wsh[k];
#pragma unroll
            for (int j = 0; j < TOUT; ++j)
                acc[j] += xv[32 + j - k] * wk;
        }
    }

    // ---------------- Phase C: epilogue -----------------------------------
    const float4* xrow = (const float4*)(x + (size_t)n * T_LEN);
    float4*       orow = (float4*)(out + (size_t)n * T_LEN);
#pragma unroll
    for (int q = 0; q < 4; ++q) {
        float4 a = xrow[4 * tid + q];
        a.x += acc[4 * q + 0];
        a.y += acc[4 * q + 1];
        a.z += acc[4 * q + 2];
        a.w += acc[4 * q + 3];
        orow[4 * tid + q] = a;
    }
}

// ---------------------------------------------------------------------------
extern "C" void kernel_launch(void* const* d_in, const int* in_sizes, int n_in,
                              void* d_out, int out_size) {
    const float* x   = (const float*)d_in[0];
    const float* w   = (const float*)d_in[1];
    const int*   src = (const int*)d_in[2];
    const int*   dst = (const int*)d_in[3];
    float*       out = (float*)d_out;

    conv_route_kernel<<<N_ROWS, TPB>>>(x, w, src, dst, out);
}

// round 3
// speedup vs baseline: 1.2368x; 1.2368x over previous
#include <cuda_runtime.h>

#define N_ROWS 1024
#define T_LEN  2048
#define E_NUM  16384
#define K_TAPS 32
#define TPB    128            // threads per block
#define TOUT   16             // outputs (t values) per thread, contiguous
#define MAX_B  96             // max experts per dst bucket

// Bank swizzle on float4 index: conflict-free for lane-stride-1 (staging stores,
// base ≡ 0/8 mod 32) AND lane-stride-4 (window loads, any offset). Bijection.
__device__ __forceinline__ int sw(int f4) { return f4 ^ ((f4 >> 2) & 7); }

// ---------------------------------------------------------------------------
// One block per dst row n. Phase A: scan dst[] (64KB, cache-resident), build
// this row's expert list in smem (ascending e -> deterministic). Phase B: per
// expert, stage x[src[e]] in swizzled smem (register double-buffered), causal
// depthwise conv, accumulate in registers. Phase C: out = x[n] + acc.
// ---------------------------------------------------------------------------
__global__ __launch_bounds__(TPB, 5)
void conv_route_kernel(const float* __restrict__ x,
                       const float* __restrict__ w,
                       const int*   __restrict__ src,
                       const int*   __restrict__ dst,
                       float*       __restrict__ out) {
    __shared__ __align__(128) float4 xs4[8 + T_LEN / 4]; // swizzled: logical xs[32+2048], halo=0
    __shared__ __align__(16)  float  wsh[K_TAPS];
    __shared__ int lst[MAX_B];
    __shared__ int scn[TPB];

    const int tid = threadIdx.x;
    const int n   = blockIdx.x;

    if (tid < 8) xs4[sw(tid)] = make_float4(0.f, 0.f, 0.f, 0.f);  // causal halo

    // ---------------- Phase A: routing discovery --------------------------
    const int4* d4 = (const int4*)dst;
    int cnt = 0;
#pragma unroll 8
    for (int c = 0; c < 32; ++c) {
        int4 v = d4[tid * 32 + c];
        cnt += (v.x == n) + (v.y == n) + (v.z == n) + (v.w == n);
    }
    scn[tid] = cnt;
    __syncthreads();
    for (int ofs = 1; ofs < TPB; ofs <<= 1) {        // Hillis-Steele scan
        int a = (tid >= ofs) ? scn[tid - ofs] : 0;
        __syncthreads();
        scn[tid] += a;
        __syncthreads();
    }
    int excl  = scn[tid] - cnt;
    int total = scn[TPB - 1];
    if (total > MAX_B) total = MAX_B;                // OOB guard
    {
        int pos = excl;
#pragma unroll 8
        for (int c = 0; c < 32; ++c) {
            int4 v = d4[tid * 32 + c];
            int  e0 = tid * 128 + c * 4;
            if (v.x == n && pos < MAX_B) lst[pos++] = e0;
            if (v.y == n && pos < MAX_B) lst[pos++] = e0 + 1;
            if (v.z == n && pos < MAX_B) lst[pos++] = e0 + 2;
            if (v.w == n && pos < MAX_B) lst[pos++] = e0 + 3;
        }
    }
    __syncthreads();

    // ---------------- Phase B: conv + accumulate --------------------------
    float acc[TOUT];
#pragma unroll
    for (int j = 0; j < TOUT; ++j) acc[j] = 0.0f;

    float4 s0, s1, s2, s3;                           // prefetch double-buffer
    float  wreg = 0.0f;
    if (0 < total) {
        int e = lst[0];
        const float4* row = (const float4*)(x + (size_t)src[e] * T_LEN);
        s0 = row[tid];
        s1 = row[tid + 128];
        s2 = row[tid + 256];
        s3 = row[tid + 384];
        if (tid < K_TAPS) wreg = w[e * K_TAPS + tid];
    }

    const float4* wsh4 = (const float4*)wsh;

    for (int i = 0; i < total; ++i) {
        __syncthreads();                              // prior window reads done
        xs4[sw(8 + tid      )] = s0;                  // publish row (swizzled)
        xs4[sw(8 + tid + 128)] = s1;
        xs4[sw(8 + tid + 256)] = s2;
        xs4[sw(8 + tid + 384)] = s3;
        if (tid < K_TAPS) wsh[tid] = wreg;
        __syncthreads();

        if (i + 1 < total) {                          // prefetch next expert
            int e = lst[i + 1];
            const float4* row = (const float4*)(x + (size_t)src[e] * T_LEN);
            s0 = row[tid];
            s1 = row[tid + 128];
            s2 = row[tid + 256];
            s3 = row[tid + 384];
            if (tid < K_TAPS) wreg = w[e * K_TAPS + tid];
        }

        // Thread owns t0 = 16*tid .. t0+15. Logical window floats t0..t0+47
        // live at float4 indices F = 4*tid + c (c=0..11). Process k in two
        // halves so only 8 window float4s (32 floats) are live at a time.
        // Half h: k = 16h + (4*kq + d); uses xvv[16 + j - (4*kq + d)] where
        // xvv[i] = xs_logical[t0 + 16*(1-h) + i].
#pragma unroll
        for (int h = 0; h < 2; ++h) {
            float xvv[32];
            const int cbase = 4 * (1 - h);
#pragma unroll
            for (int c = 0; c < 8; ++c) {
                float4 v = xs4[sw(4 * tid + cbase + c)];
                xvv[4 * c + 0] = v.x; xvv[4 * c + 1] = v.y;
                xvv[4 * c + 2] = v.z; xvv[4 * c + 3] = v.w;
            }
#pragma unroll
            for (int kq = 0; kq < 4; ++kq) {
                float4 wv = wsh4[4 * h + kq];
#pragma unroll
                for (int j = 0; j < TOUT; ++j) acc[j] += xvv[16 + j - 4 * kq - 0] * wv.x;
#pragma unroll
                for (int j = 0; j < TOUT; ++j) acc[j] += xvv[15 + j - 4 * kq    ] * wv.y;
#pragma unroll
                for (int j = 0; j < TOUT; ++j) acc[j] += xvv[14 + j - 4 * kq    ] * wv.z;
#pragma unroll
                for (int j = 0; j < TOUT; ++j) acc[j] += xvv[13 + j - 4 * kq    ] * wv.w;
            }
        }
    }

    // ---------------- Phase C: epilogue -----------------------------------
    const float4* xrow = (const float4*)(x + (size_t)n * T_LEN);
    float4*       orow = (float4*)(out + (size_t)n * T_LEN);
#pragma unroll
    for (int q = 0; q < 4; ++q) {
        float4 a = xrow[4 * tid + q];
        a.x += acc[4 * q + 0];
        a.y += acc[4 * q + 1];
        a.z += acc[4 * q + 2];
        a.w += acc[4 * q + 3];
        orow[4 * tid + q] = a;
    }
}

// ---------------------------------------------------------------------------
extern "C" void kernel_launch(void* const* d_in, const int* in_sizes, int n_in,
                              void* d_out, int out_size) {
    const float* x   = (const float*)d_in[0];
    const float* w   = (const float*)d_in[1];
    const int*   src = (const int*)d_in[2];
    const int*   dst = (const int*)d_in[3];
    float*       out = (float*)d_out;

    conv_route_kernel<<<N_ROWS, TPB>>>(x, w, src, dst, out);
}